// round 1
// baseline (speedup 1.0000x reference)
#include <cuda_runtime.h>

// FineMatching: M x (64x100x64 GEMM + dual softmax + argmax + 3x3 window softmax)
// One CTA per m, 128 threads, packed fma.rn.f32x2 math, smem-staged operands.

#define TPB 128
#define SA 68    // At stride [c][l], multiple of 4 for 16B-aligned ulonglong2 reads
#define SB 113   // Bt stride [c][r], odd -> conflict-free transpose writes; r zero-padded to 112
#define SE 66    // Ef/Ff stride [r][l], even -> 8B-aligned float2 stores
#define SP 65    // prow stride
#define SC 101   // pcol stride

#define OFF_AT   0        // 64*68  = 4352
#define OFF_BT   4352     // 64*113 = 7232
#define OFF_EF   11584    // 100*66 = 6600
#define OFF_FF   18184    // 100*66 = 6600
#define OFF_PROW 24784    // 16*65  = 1040
#define OFF_PCOL 25824    // 8*101  = 808
#define OFF_IROW 26632    // 64
#define OFF_ICOL 26696    // 100
#define OFF_RED  26796    // 16
#define SMEM_FLOATS 26812
#define SMEM_BYTES  (SMEM_FLOATS * 4)

__device__ __forceinline__ unsigned long long pack2(float x, float y) {
    unsigned long long r;
    asm("mov.b64 %0, {%1, %2};" : "=l"(r) : "f"(x), "f"(y));
    return r;
}
__device__ __forceinline__ void unpack2(unsigned long long v, float& x, float& y) {
    asm("mov.b64 {%0, %1}, %2;" : "=f"(x), "=f"(y) : "l"(v));
}
__device__ __forceinline__ void ffma2(unsigned long long& d, unsigned long long a, unsigned long long b) {
    asm("fma.rn.f32x2 %0, %1, %2, %0;" : "+l"(d) : "l"(a), "l"(b));
}

__global__ __launch_bounds__(TPB, 2)
void fine_matching_kernel(const float* __restrict__ feat0,
                          const float* __restrict__ feat1,
                          const float* __restrict__ mk0c,
                          const float* __restrict__ mk1c,
                          const int*   __restrict__ hw0i,
                          const int*   __restrict__ hw0f,
                          float* __restrict__ out_mk0,
                          float* __restrict__ out_mk1,
                          float* __restrict__ out_probs,
                          float* __restrict__ out_sm)
{
    extern __shared__ float smem[];
    float* At     = smem + OFF_AT;    // [64][SA]  feat0 transposed: At[c][l]
    float* Bt     = smem + OFF_BT;    // [64][SB]  feat1 transposed: Bt[c][r], r<112
    float* Ef     = smem + OFF_EF;    // [100][SE] exp(conf_f - gmax), [r][l]
    float* Ff     = smem + OFF_FF;    // [100][SE] conf_ff, [r][l]
    float* prow   = smem + OFF_PROW;  // [16][SP]
    float* pcol   = smem + OFF_PCOL;  // [8][SC]
    float* invRow = smem + OFF_IROW;  // [64]
    float* invCol = smem + OFF_ICOL;  // [100]
    float* red    = smem + OFF_RED;   // [16] scratch

    const int m   = blockIdx.x;
    const int tid = threadIdx.x;

    // ------------------ load + transpose operands into smem ------------------
    {
        const float4* f0 = reinterpret_cast<const float4*>(feat0 + (size_t)m * 4096);
        #pragma unroll 4
        for (int idx = tid; idx < 1024; idx += TPB) {
            float4 v = f0[idx];
            int l = idx >> 4, c4 = (idx & 15) << 2;
            At[(c4 + 0) * SA + l] = v.x;
            At[(c4 + 1) * SA + l] = v.y;
            At[(c4 + 2) * SA + l] = v.z;
            At[(c4 + 3) * SA + l] = v.w;
        }
        const float4* f1 = reinterpret_cast<const float4*>(feat1 + (size_t)m * 6400);
        #pragma unroll 4
        for (int idx = tid; idx < 1600; idx += TPB) {
            float4 v = f1[idx];
            int r = idx >> 4, c4 = (idx & 15) << 2;
            Bt[(c4 + 0) * SB + r] = v.x;
            Bt[(c4 + 1) * SB + r] = v.y;
            Bt[(c4 + 2) * SB + r] = v.z;
            Bt[(c4 + 3) * SB + r] = v.w;
        }
        // zero-pad r in [100,112) so padded accumulators stay clean
        for (int idx = tid; idx < 64 * 13; idx += TPB) {
            int c = idx / 13, r = 100 + idx - c * 13;
            Bt[c * SB + r] = 0.0f;
        }
    }
    __syncthreads();

    const int tx = tid & 7;    // l groups: l in {4tx..4tx+3} u {32+4tx..32+4tx+3}
    const int ty = tid >> 3;   // r = ty + 16j, j<7 (r<112, valid if <100)

    unsigned long long acc[4][7];
    #pragma unroll
    for (int p = 0; p < 4; p++)
        #pragma unroll
        for (int j = 0; j < 7; j++) acc[p][j] = 0ULL;

    // ------------------ GEMM pass 1: channels 0..55 (conf_f) ------------------
    #pragma unroll 4
    for (int c = 0; c < 56; c++) {
        const float* arow = At + c * SA + (tx << 2);
        ulonglong2 aLo = *reinterpret_cast<const ulonglong2*>(arow);        // l: 4tx..4tx+3
        ulonglong2 aHi = *reinterpret_cast<const ulonglong2*>(arow + 32);   // l: 32+4tx..
        const float* brow = Bt + c * SB + ty;
        #pragma unroll
        for (int j = 0; j < 7; j++) {
            float b = brow[j << 4];
            unsigned long long bb = pack2(b, b);
            ffma2(acc[0][j], aLo.x, bb);
            ffma2(acc[1][j], aLo.y, bb);
            ffma2(acc[2][j], aHi.x, bb);
            ffma2(acc[3][j], aHi.y, bb);
        }
    }

    // local max of raw sums (conf_f = sum/64, positive scale preserves argmax of max)
    float lmax = -3.0e38f;
    #pragma unroll
    for (int p = 0; p < 4; p++)
        #pragma unroll
        for (int j = 0; j < 7; j++) {
            int r = ty + (j << 4);
            if (r < 100) {
                float x, y; unpack2(acc[p][j], x, y);
                lmax = fmaxf(lmax, fmaxf(x, y));
            }
        }
    #pragma unroll
    for (int off = 16; off; off >>= 1)
        lmax = fmaxf(lmax, __shfl_xor_sync(0xffffffffu, lmax, off));
    if ((tid & 31) == 0) red[tid >> 5] = lmax;
    __syncthreads();
    if (tid == 0)
        red[8] = fmaxf(fmaxf(red[0], red[1]), fmaxf(red[2], red[3])) * (1.0f / 64.0f);
    __syncthreads();
    const float gmax = red[8];

    // E = exp(conf_f - gmax); store to Ef[r][l]; accumulate row/col partial sums
    const float inv64 = 1.0f / 64.0f;
    {
        float rs[8];
        #pragma unroll
        for (int i = 0; i < 8; i++) rs[i] = 0.0f;
        float cs[7];
        #pragma unroll
        for (int j = 0; j < 7; j++) cs[j] = 0.0f;

        #pragma unroll
        for (int p = 0; p < 4; p++) {
            int l = ((p >> 1) << 5) | (tx << 2) | ((p & 1) << 1);
            #pragma unroll
            for (int j = 0; j < 7; j++) {
                int r = ty + (j << 4);
                if (r < 100) {
                    float x, y; unpack2(acc[p][j], x, y);
                    float e0 = __expf(fmaf(x, inv64, -gmax));
                    float e1 = __expf(fmaf(y, inv64, -gmax));
                    *reinterpret_cast<float2*>(&Ef[r * SE + l]) = make_float2(e0, e1);
                    rs[2 * p]     += e0;
                    rs[2 * p + 1] += e1;
                    cs[j]         += e0 + e1;
                }
            }
        }
        #pragma unroll
        for (int p = 0; p < 4; p++) {
            int l = ((p >> 1) << 5) | (tx << 2) | ((p & 1) << 1);
            prow[ty * SP + l]     = rs[2 * p];
            prow[ty * SP + l + 1] = rs[2 * p + 1];
        }
        #pragma unroll
        for (int j = 0; j < 7; j++) {
            int r = ty + (j << 4);
            if (r < 100) pcol[tx * SC + r] = cs[j];
        }
    }

    // ------------------ GEMM pass 2: channels 56..63 (conf_ff) ------------------
    #pragma unroll
    for (int p = 0; p < 4; p++)
        #pragma unroll
        for (int j = 0; j < 7; j++) acc[p][j] = 0ULL;

    #pragma unroll
    for (int c = 56; c < 64; c++) {
        const float* arow = At + c * SA + (tx << 2);
        ulonglong2 aLo = *reinterpret_cast<const ulonglong2*>(arow);
        ulonglong2 aHi = *reinterpret_cast<const ulonglong2*>(arow + 32);
        const float* brow = Bt + c * SB + ty;
        #pragma unroll
        for (int j = 0; j < 7; j++) {
            float b = brow[j << 4];
            unsigned long long bb = pack2(b, b);
            ffma2(acc[0][j], aLo.x, bb);
            ffma2(acc[1][j], aLo.y, bb);
            ffma2(acc[2][j], aHi.x, bb);
            ffma2(acc[3][j], aHi.y, bb);
        }
    }
    {
        const float rs8 = 0.35355339059327376f;  // 1/sqrt(8)
        #pragma unroll
        for (int p = 0; p < 4; p++) {
            int l = ((p >> 1) << 5) | (tx << 2) | ((p & 1) << 1);
            #pragma unroll
            for (int j = 0; j < 7; j++) {
                int r = ty + (j << 4);
                if (r < 100) {
                    float x, y; unpack2(acc[p][j], x, y);
                    *reinterpret_cast<float2*>(&Ff[r * SE + l]) = make_float2(x * rs8, y * rs8);
                }
            }
        }
    }
    __syncthreads();

    // ------------------ softmax denominators ------------------
    if (tid < 64) {
        float s = 0.0f;
        #pragma unroll
        for (int t = 0; t < 16; t++) s += prow[t * SP + tid];
        invRow[tid] = 1.0f / s;
    }
    if (tid < 100) {
        float s = 0.0f;
        #pragma unroll
        for (int t = 0; t < 8; t++) s += pcol[t * SC + tid];
        invCol[tid] = 1.0f / s;
    }
    __syncthreads();

    // ------------------ sm output + argmax (first-index tie-break) ------------------
    float best = -1.0f;
    int   bidx = 0;
    float* smo = out_sm + (size_t)m * 4096;
    #pragma unroll
    for (int f = tid; f < 4096; f += TPB) {
        int l = f >> 6, k = f & 63;
        int r = 11 + ((k >> 3) * 10) + (k & 7);  // inner crop [1:-1,1:-1] of 10x10
        float e = Ef[r * SE + l];
        float v = e * e * invRow[l] * invCol[r];
        smo[f] = v;
        if (v > best) { best = v; bidx = f; }
    }
    #pragma unroll
    for (int off = 16; off; off >>= 1) {
        float ov = __shfl_xor_sync(0xffffffffu, best, off);
        int   oi = __shfl_xor_sync(0xffffffffu, bidx, off);
        if (ov > best || (ov == best && oi < bidx)) { best = ov; bidx = oi; }
    }
    if ((tid & 31) == 0) {
        red[4 + (tid >> 5)] = best;
        reinterpret_cast<int*>(red)[8 + (tid >> 5)] = bidx;
    }
    __syncthreads();
    if (tid == 0) {
        float bv = red[4];
        int   bi = reinterpret_cast<int*>(red)[8];
        #pragma unroll
        for (int w2 = 1; w2 < 4; w2++) {
            float ov = red[4 + w2];
            int   oi = reinterpret_cast<int*>(red)[8 + w2];
            if (ov > bv || (ov == bv && oi < bi)) { bv = ov; bi = oi; }
        }
        reinterpret_cast<int*>(red)[12] = bi;
    }
    __syncthreads();
    const int idx = reinterpret_cast<int*>(red)[12];

    // ------------------ epilogue: window softmax + keypoints (warp 0) ------------------
    if (tid < 32) {
        const int idx_l = idx >> 6;
        const int idx_r = idx & 63;
        const float scl = (float)(*hw0i) / (float)(*hw0f);

        const int  di    = tid / 3;
        const int  dj    = tid - di * 3;
        const bool valid = tid < 9;

        float w = -3.0e38f;
        if (valid) {
            int wi = (idx_r >> 3) + di - 1; if (wi < 0) wi += 10;
            int wj = (idx_r & 7)  + dj - 1; if (wj < 0) wj += 10;
            w = Ff[(wi * 10 + wj) * SE + idx_l];
        }
        float mx = w;
        #pragma unroll
        for (int off = 16; off; off >>= 1)
            mx = fmaxf(mx, __shfl_xor_sync(0xffffffffu, mx, off));
        float t = valid ? __expf((w - mx) * 0.1f) : 0.0f;   // TEMP = 10
        float s = t;
        #pragma unroll
        for (int off = 16; off; off >>= 1)
            s += __shfl_xor_sync(0xffffffffu, s, off);
        float pr = t / s;
        if (valid) out_probs[(size_t)m * 9 + tid] = pr;

        float cx = valid ? pr * (float)(dj - 1) : 0.0f;
        float cy = valid ? pr * (float)(di - 1) : 0.0f;
        #pragma unroll
        for (int off = 16; off; off >>= 1) {
            cx += __shfl_xor_sync(0xffffffffu, cx, off);
            cy += __shfl_xor_sync(0xffffffffu, cy, off);
        }
        if (tid == 0) {
            float m0x = mk0c[2 * m], m0y = mk0c[2 * m + 1];
            float m1x = mk1c[2 * m], m1y = mk1c[2 * m + 1];
            out_mk0[2 * m]     = fmaf((float)(idx_l & 7) - 3.5f, scl, m0x);
            out_mk0[2 * m + 1] = fmaf((float)(idx_l >> 3) - 3.5f, scl, m0y);
            out_mk1[2 * m]     = m1x + ((float)(idx_r & 7) - 3.5f) * scl + cx * scl;
            out_mk1[2 * m + 1] = m1y + ((float)(idx_r >> 3) - 3.5f) * scl + cy * scl;
        }
    }
}

extern "C" void kernel_launch(void* const* d_in, const int* in_sizes, int n_in,
                              void* d_out, int out_size) {
    const float* feat0 = (const float*)d_in[0];
    const float* feat1 = (const float*)d_in[1];
    const float* mk0c  = (const float*)d_in[2];
    const float* mk1c  = (const float*)d_in[3];
    // d_in[4] = mconf (unused), d_in[5] = b_ids (unused)
    const int* hw0i = (const int*)d_in[6];  // low 32 bits valid for int32 or LE int64
    const int* hw0f = (const int*)d_in[7];

    const int M = in_sizes[0] / 4096;  // feat_0 is (M, 64, 64)

    float* out       = (float*)d_out;
    float* out_mk0   = out;                     // (M,2)
    float* out_mk1   = out + (size_t)2 * M;     // (M,2)
    float* out_probs = out + (size_t)4 * M;     // (M,9)
    float* out_sm    = out + (size_t)13 * M;    // (M,64,64)

    cudaFuncSetAttribute(fine_matching_kernel,
                         cudaFuncAttributeMaxDynamicSharedMemorySize, SMEM_BYTES);
    fine_matching_kernel<<<M, TPB, SMEM_BYTES>>>(
        feat0, feat1, mk0c, mk1c, hw0i, hw0f,
        out_mk0, out_mk1, out_probs, out_sm);
}

// round 2
// speedup vs baseline: 1.5731x; 1.5731x over previous
#include <cuda_runtime.h>

// FineMatching: M x (64x100x56 GEMM + dual softmax + argmax + lazy 3x3 window softmax)
// One CTA per m, 128 threads, packed fma.rn.f32x2 math.
// R2: smem cut 107KB -> 54.4KB (Ef aliases At/Bt; conf_ff GEMM replaced by lazy
//     9-dot epilogue) => 4 CTAs/SM instead of 2.

#define TPB 128
#define SA 68    // At/Aff stride [c][l]
#define SB 113   // Bt/Bff stride [c][r], odd -> conflict-free transpose writes
#define SE 66    // Ef stride [r][l]
#define SP 65    // prow stride
#define SC 101   // pcol stride

#define OFF_AT   0        // 56*68  = 3808   (pass-1 channels only)
#define OFF_BT   3808     // 56*113 = 6328   -> end 10136
#define OFF_EF   0        // 100*66 = 6600   ALIASES At/Bt (dead after GEMM)
#define OFF_AFF  10136    // 8*68   = 544    (channels 56..63 of feat0)
#define OFF_BFF  10680    // 8*113  = 904    (channels 56..63 of feat1)
#define OFF_PROW 11584    // 16*65  = 1040
#define OFF_PCOL 12624    // 8*101  = 808
#define OFF_IROW 13432    // 64
#define OFF_ICOL 13496    // 100
#define OFF_RED  13596    // 16
#define SMEM_FLOATS 13612
#define SMEM_BYTES  (SMEM_FLOATS * 4)   // 54448 B -> 4 CTAs/SM

__device__ __forceinline__ unsigned long long pack2(float x, float y) {
    unsigned long long r;
    asm("mov.b64 %0, {%1, %2};" : "=l"(r) : "f"(x), "f"(y));
    return r;
}
__device__ __forceinline__ void unpack2(unsigned long long v, float& x, float& y) {
    asm("mov.b64 {%0, %1}, %2;" : "=f"(x), "=f"(y) : "l"(v));
}
__device__ __forceinline__ void ffma2(unsigned long long& d, unsigned long long a, unsigned long long b) {
    asm("fma.rn.f32x2 %0, %1, %2, %0;" : "+l"(d) : "l"(a), "l"(b));
}

__global__ __launch_bounds__(TPB, 4)
void fine_matching_kernel(const float* __restrict__ feat0,
                          const float* __restrict__ feat1,
                          const float* __restrict__ mk0c,
                          const float* __restrict__ mk1c,
                          const int*   __restrict__ hw0i,
                          const int*   __restrict__ hw0f,
                          float* __restrict__ out_mk0,
                          float* __restrict__ out_mk1,
                          float* __restrict__ out_probs,
                          float* __restrict__ out_sm)
{
    extern __shared__ float smem[];
    float* At     = smem + OFF_AT;    // [56][SA]  feat0[c][l], c<56
    float* Bt     = smem + OFF_BT;    // [56][SB]  feat1[c][r], c<56, r<112 padded
    float* Ef     = smem + OFF_EF;    // [100][SE] exp(conf_f - gmax)  (aliases At/Bt)
    float* Aff    = smem + OFF_AFF;   // [8][SA]   feat0 channels 56..63
    float* Bff    = smem + OFF_BFF;   // [8][SB]   feat1 channels 56..63
    float* prow   = smem + OFF_PROW;
    float* pcol   = smem + OFF_PCOL;
    float* invRow = smem + OFF_IROW;
    float* invCol = smem + OFF_ICOL;
    float* red    = smem + OFF_RED;

    const int m   = blockIdx.x;
    const int tid = threadIdx.x;

    // ------------------ load + transpose operands into smem ------------------
    {
        const float4* f0 = reinterpret_cast<const float4*>(feat0 + (size_t)m * 4096);
        #pragma unroll 4
        for (int idx = tid; idx < 1024; idx += TPB) {
            float4 v = f0[idx];
            int l = idx >> 4, c4 = (idx & 15) << 2;
            float* dst = (c4 < 56) ? (At + c4 * SA + l) : (Aff + (c4 - 56) * SA + l);
            dst[0 * SA] = v.x;
            dst[1 * SA] = v.y;
            dst[2 * SA] = v.z;
            dst[3 * SA] = v.w;
        }
        const float4* f1 = reinterpret_cast<const float4*>(feat1 + (size_t)m * 6400);
        #pragma unroll 4
        for (int idx = tid; idx < 1600; idx += TPB) {
            float4 v = f1[idx];
            int r = idx >> 4, c4 = (idx & 15) << 2;
            float* dst = (c4 < 56) ? (Bt + c4 * SB + r) : (Bff + (c4 - 56) * SB + r);
            dst[0 * SB] = v.x;
            dst[1 * SB] = v.y;
            dst[2 * SB] = v.z;
            dst[3 * SB] = v.w;
        }
        // zero-pad r in [100,112) for the 56 GEMM channels
        for (int idx = tid; idx < 56 * 13; idx += TPB) {
            int c = idx / 13, r = 100 + idx - c * 13;
            Bt[c * SB + r] = 0.0f;
        }
    }
    __syncthreads();

    const int tx = tid & 7;    // l groups: {4tx..4tx+3} u {32+4tx..32+4tx+3}
    const int ty = tid >> 3;   // r = ty + 16j, j<7

    unsigned long long acc[4][7];
    #pragma unroll
    for (int p = 0; p < 4; p++)
        #pragma unroll
        for (int j = 0; j < 7; j++) acc[p][j] = 0ULL;

    // ------------------ GEMM: channels 0..55 (conf_f) ------------------
    #pragma unroll 4
    for (int c = 0; c < 56; c++) {
        const float* arow = At + c * SA + (tx << 2);
        ulonglong2 aLo = *reinterpret_cast<const ulonglong2*>(arow);
        ulonglong2 aHi = *reinterpret_cast<const ulonglong2*>(arow + 32);
        const float* brow = Bt + c * SB + ty;
        #pragma unroll
        for (int j = 0; j < 7; j++) {
            float b = brow[j << 4];
            unsigned long long bb = pack2(b, b);
            ffma2(acc[0][j], aLo.x, bb);
            ffma2(acc[1][j], aLo.y, bb);
            ffma2(acc[2][j], aHi.x, bb);
            ffma2(acc[3][j], aHi.y, bb);
        }
    }

    // global max of raw sums (conf_f = sum/64; positive scale preserves max)
    float lmax = -3.0e38f;
    #pragma unroll
    for (int p = 0; p < 4; p++)
        #pragma unroll
        for (int j = 0; j < 7; j++) {
            int r = ty + (j << 4);
            if (r < 100) {
                float x, y; unpack2(acc[p][j], x, y);
                lmax = fmaxf(lmax, fmaxf(x, y));
            }
        }
    #pragma unroll
    for (int off = 16; off; off >>= 1)
        lmax = fmaxf(lmax, __shfl_xor_sync(0xffffffffu, lmax, off));
    if ((tid & 31) == 0) red[tid >> 5] = lmax;
    __syncthreads();   // also: all warps done reading At/Bt -> Ef alias is safe
    if (tid == 0)
        red[8] = fmaxf(fmaxf(red[0], red[1]), fmaxf(red[2], red[3])) * (1.0f / 64.0f);
    __syncthreads();
    const float gmax = red[8];

    // E = exp(conf_f - gmax) -> Ef[r][l] (aliased over At/Bt); partial row/col sums
    const float inv64 = 1.0f / 64.0f;
    {
        float rs[8];
        #pragma unroll
        for (int i = 0; i < 8; i++) rs[i] = 0.0f;
        float cs[7];
        #pragma unroll
        for (int j = 0; j < 7; j++) cs[j] = 0.0f;

        #pragma unroll
        for (int p = 0; p < 4; p++) {
            int l = ((p >> 1) << 5) | (tx << 2) | ((p & 1) << 1);
            #pragma unroll
            for (int j = 0; j < 7; j++) {
                int r = ty + (j << 4);
                if (r < 100) {
                    float x, y; unpack2(acc[p][j], x, y);
                    float e0 = __expf(fmaf(x, inv64, -gmax));
                    float e1 = __expf(fmaf(y, inv64, -gmax));
                    *reinterpret_cast<float2*>(&Ef[r * SE + l]) = make_float2(e0, e1);
                    rs[2 * p]     += e0;
                    rs[2 * p + 1] += e1;
                    cs[j]         += e0 + e1;
                }
            }
        }
        #pragma unroll
        for (int p = 0; p < 4; p++) {
            int l = ((p >> 1) << 5) | (tx << 2) | ((p & 1) << 1);
            prow[ty * SP + l]     = rs[2 * p];
            prow[ty * SP + l + 1] = rs[2 * p + 1];
        }
        #pragma unroll
        for (int j = 0; j < 7; j++) {
            int r = ty + (j << 4);
            if (r < 100) pcol[tx * SC + r] = cs[j];
        }
    }
    __syncthreads();

    // ------------------ softmax denominators ------------------
    if (tid < 64) {
        float s = 0.0f;
        #pragma unroll
        for (int t = 0; t < 16; t++) s += prow[t * SP + tid];
        invRow[tid] = 1.0f / s;
    }
    if (tid < 100) {
        float s = 0.0f;
        #pragma unroll
        for (int t = 0; t < 8; t++) s += pcol[t * SC + tid];
        invCol[tid] = 1.0f / s;
    }
    __syncthreads();

    // ------------------ sm output + argmax (first-index tie-break) ------------------
    float best = -1.0f;
    int   bidx = 0;
    float* smo = out_sm + (size_t)m * 4096;
    #pragma unroll
    for (int f = tid; f < 4096; f += TPB) {
        int l = f >> 6, k = f & 63;
        int r = 11 + ((k >> 3) * 10) + (k & 7);  // inner crop [1:-1,1:-1] of 10x10
        float e = Ef[r * SE + l];
        float v = e * e * invRow[l] * invCol[r];
        smo[f] = v;
        if (v > best) { best = v; bidx = f; }
    }
    #pragma unroll
    for (int off = 16; off; off >>= 1) {
        float ov = __shfl_xor_sync(0xffffffffu, best, off);
        int   oi = __shfl_xor_sync(0xffffffffu, bidx, off);
        if (ov > best || (ov == best && oi < bidx)) { best = ov; bidx = oi; }
    }
    if ((tid & 31) == 0) {
        red[4 + (tid >> 5)] = best;
        reinterpret_cast<int*>(red)[8 + (tid >> 5)] = bidx;
    }
    __syncthreads();
    if (tid == 0) {
        float bv = red[4];
        int   bi = reinterpret_cast<int*>(red)[8];
        #pragma unroll
        for (int w2 = 1; w2 < 4; w2++) {
            float ov = red[4 + w2];
            int   oi = reinterpret_cast<int*>(red)[8 + w2];
            if (ov > bv || (ov == bv && oi < bi)) { bv = ov; bi = oi; }
        }
        reinterpret_cast<int*>(red)[12] = bi;
    }
    __syncthreads();
    const int idx = reinterpret_cast<int*>(red)[12];

    // ------------------ epilogue: lazy conf_ff window + softmax + keypoints ------------------
    if (tid < 32) {
        const int idx_l = idx >> 6;
        const int idx_r = idx & 63;
        const float scl = (float)(*hw0i) / (float)(*hw0f);
        const float rs8 = 0.35355339059327376f;  // 1/sqrt(8)

        const int  di    = tid / 3;
        const int  dj    = tid - di * 3;
        const bool valid = tid < 9;

        float w = -3.0e38f;
        if (valid) {
            int wi = (idx_r >> 3) + di - 1; if (wi < 0) wi += 10;
            int wj = (idx_r & 7)  + dj - 1; if (wj < 0) wj += 10;
            int wr = wi * 10 + wj;
            float dot = 0.0f;
            #pragma unroll
            for (int c = 0; c < 8; c++)
                dot = fmaf(Aff[c * SA + idx_l], Bff[c * SB + wr], dot);
            w = dot * rs8;
        }
        float mx = w;
        #pragma unroll
        for (int off = 16; off; off >>= 1)
            mx = fmaxf(mx, __shfl_xor_sync(0xffffffffu, mx, off));
        float t = valid ? __expf((w - mx) * 0.1f) : 0.0f;   // TEMP = 10
        float s = t;
        #pragma unroll
        for (int off = 16; off; off >>= 1)
            s += __shfl_xor_sync(0xffffffffu, s, off);
        float pr = t / s;
        if (valid) out_probs[(size_t)m * 9 + tid] = pr;

        float cx = valid ? pr * (float)(dj - 1) : 0.0f;
        float cy = valid ? pr * (float)(di - 1) : 0.0f;
        #pragma unroll
        for (int off = 16; off; off >>= 1) {
            cx += __shfl_xor_sync(0xffffffffu, cx, off);
            cy += __shfl_xor_sync(0xffffffffu, cy, off);
        }
        if (tid == 0) {
            float m0x = mk0c[2 * m], m0y = mk0c[2 * m + 1];
            float m1x = mk1c[2 * m], m1y = mk1c[2 * m + 1];
            out_mk0[2 * m]     = fmaf((float)(idx_l & 7) - 3.5f, scl, m0x);
            out_mk0[2 * m + 1] = fmaf((float)(idx_l >> 3) - 3.5f, scl, m0y);
            out_mk1[2 * m]     = m1x + ((float)(idx_r & 7) - 3.5f) * scl + cx * scl;
            out_mk1[2 * m + 1] = m1y + ((float)(idx_r >> 3) - 3.5f) * scl + cy * scl;
        }
    }
}

extern "C" void kernel_launch(void* const* d_in, const int* in_sizes, int n_in,
                              void* d_out, int out_size) {
    const float* feat0 = (const float*)d_in[0];
    const float* feat1 = (const float*)d_in[1];
    const float* mk0c  = (const float*)d_in[2];
    const float* mk1c  = (const float*)d_in[3];
    // d_in[4] = mconf (unused), d_in[5] = b_ids (unused)
    const int* hw0i = (const int*)d_in[6];
    const int* hw0f = (const int*)d_in[7];

    const int M = in_sizes[0] / 4096;

    float* out       = (float*)d_out;
    float* out_mk0   = out;
    float* out_mk1   = out + (size_t)2 * M;
    float* out_probs = out + (size_t)4 * M;
    float* out_sm    = out + (size_t)13 * M;

    cudaFuncSetAttribute(fine_matching_kernel,
                         cudaFuncAttributeMaxDynamicSharedMemorySize, SMEM_BYTES);
    fine_matching_kernel<<<M, TPB, SMEM_BYTES>>>(
        feat0, feat1, mk0c, mk1c, hw0i, hw0f,
        out_mk0, out_mk1, out_probs, out_sm);
}